// round 7
// baseline (speedup 1.0000x reference)
#include <cuda_runtime.h>
#include <cuda_bf16.h>
#include <math.h>
#include <stdint.h>

#define H_HEADS   32
#define KV_HEADS  8
#define DIM       128
#define PAGE      16
#define TOPK      256
#define HID       4096
#define QKV_N     6144         // 4096 q + 1024 k + 1024 v
#define SPLIT     128          // K-chunks of 32 rows
#define MAXPAGES  2048
#define NCHUNK    32           // flash-decode chunks per head
#define PPC       8            // pages per chunk
#define TPC       128          // tokens per chunk

extern "C" __device__ float __nv_powf(float, float);

// -------- device scratch (symbols only referenced inside kernels!) --------
__device__ float g_partial[SPLIT * QKV_N];
__device__ float g_qkv[QKV_N];                 // [0,4096)=q, [4096,5120)=k, [5120,6144)=v
__device__ float g_kmax[MAXPAGES * KV_HEADS * DIM];   // 8MB
__device__ float g_kmin[MAXPAGES * KV_HEADS * DIM];   // 8MB
__device__ float g_scores[H_HEADS * MAXPAGES];
__device__ int   g_topk[H_HEADS * TOPK];
__device__ float g_m[H_HEADS * NCHUNK];
__device__ float g_l[H_HEADS * NCHUNK];
__device__ float g_acc[H_HEADS * NCHUNK * DIM];

// -------- streams/events for graph fork (created once, before any capture) --------
static cudaStream_t s_side;
static cudaEvent_t  s_evFork, s_evJoin;
static struct StreamInit {
    StreamInit() {
        cudaStreamCreateWithFlags(&s_side, cudaStreamNonBlocking);
        cudaEventCreateWithFlags(&s_evFork, cudaEventDisableTiming);
        cudaEventCreateWithFlags(&s_evJoin, cudaEventDisableTiming);
    }
} s_streamInit;

// ======================== fused QKV split-K GEMV (float4) ========================
__global__ void gemv_qkv_k(const float* __restrict__ Wq, const float* __restrict__ Wk,
                           const float* __restrict__ Wv, const float* __restrict__ x) {
    int b = blockIdx.x, tid = threadIdx.x;
    const float* W; int N4, xb, chunk, colOff4;
    if (b < 512)      { W = Wq; N4 = 1024; xb = b & 3; chunk = b >> 2;  colOff4 = 0; }
    else if (b < 640) { W = Wk; N4 = 256;  xb = 0;     chunk = b - 512; colOff4 = 1024; }
    else              { W = Wv; N4 = 256;  xb = 0;     chunk = b - 640; colOff4 = 1280; }
    __shared__ float xs[32];
    if (tid < 32) xs[tid] = x[chunk * 32 + tid];
    __syncthreads();
    int j4 = xb * 256 + tid;
    const float4* w4 = (const float4*)W + (size_t)(chunk * 32) * N4 + j4;
    float4 a = make_float4(0.f, 0.f, 0.f, 0.f);
#pragma unroll
    for (int i = 0; i < 32; ++i) {
        float4 wv = w4[(size_t)i * N4];
        float xv = xs[i];
        a.x = fmaf(xv, wv.x, a.x); a.y = fmaf(xv, wv.y, a.y);
        a.z = fmaf(xv, wv.z, a.z); a.w = fmaf(xv, wv.w, a.w);
    }
    ((float4*)g_partial)[chunk * (QKV_N / 4) + colOff4 + j4] = a;
}

// ======================== Wo GEMV with fused flash-decode combine ========================
__global__ void gemv_o_k(const float* __restrict__ Wo) {
    int b = blockIdx.x, tid = threadIdx.x;
    int xb = b & 3, chunk = b >> 2;          // chunk in [0,128)
    __shared__ float xs[32];
    if (tid < 32) {
        int h = chunk >> 2;                  // 4 chunks (32 dims each) per head
        int d = (chunk & 3) * 32 + tid;
        float M = -INFINITY;
#pragma unroll
        for (int c = 0; c < NCHUNK; ++c) M = fmaxf(M, g_m[h * NCHUNK + c]);
        float L = 0.f, acc = 0.f;
#pragma unroll
        for (int c = 0; c < NCHUNK; ++c) {
            float f = __expf(g_m[h * NCHUNK + c] - M);
            L += f * g_l[h * NCHUNK + c];
            acc += f * g_acc[(h * NCHUNK + c) * DIM + d];
        }
        xs[tid] = acc / L;
    }
    __syncthreads();
    int j4 = xb * 256 + tid;
    const float4* w4 = (const float4*)Wo + (size_t)(chunk * 32) * 1024 + j4;
    float4 a = make_float4(0.f, 0.f, 0.f, 0.f);
#pragma unroll
    for (int i = 0; i < 32; ++i) {
        float4 wv = w4[(size_t)i * 1024];
        float xv = xs[i];
        a.x = fmaf(xv, wv.x, a.x); a.y = fmaf(xv, wv.y, a.y);
        a.z = fmaf(xv, wv.z, a.z); a.w = fmaf(xv, wv.w, a.w);
    }
    ((float4*)g_partial)[chunk * (QKV_N / 4) + j4] = a;
}

// ======================== reduce partials + fused RoPE ========================
__global__ void reduce_rope_k(int past) {
    int tid = threadIdx.x;
    int e = blockIdx.x * 256 + tid;
    __shared__ float redsum[256];
    __shared__ float ctab[64], stab[64];
    if (tid < 64) {
        float ee = (float)tid / 64.0f;
        float p = __nv_powf(10000.0f, ee);
        float invf = 1.0f / p;
        float ang = (float)past * invf;
        double aa = (double)ang;
        ctab[tid] = (float)cos(aa);
        stab[tid] = (float)sin(aa);
    }
    float s = 0.f;
#pragma unroll 16
    for (int c = 0; c < SPLIT; ++c) s += g_partial[c * QKV_N + e];
    redsum[tid] = s;
    __syncthreads();
    int row = e >> 7, col = e & 127;
    float outv = s;
    if (row < 40) {                       // q rows 0-31, k rows 32-39
        float partner = redsum[tid ^ 64];
        float c = ctab[col & 63], sn = stab[col & 63];
        outv = (col < 64) ? (s * c - partner * sn) : (s * c + partner * sn);
    }
    g_qkv[e] = outv;
}

__global__ void reduce_out_k(float* __restrict__ out) {
    int j = blockIdx.x * 256 + threadIdx.x;
    float s = 0.f;
#pragma unroll 16
    for (int c = 0; c < SPLIT; ++c) s += g_partial[c * QKV_N + j];
    out[j] = s;
}

// ======================== page min/max scan (q-independent, runs on side stream) ====
__global__ void minmax_k(const float* __restrict__ kc) {
    int p = blockIdx.x;
    int tid = threadIdx.x;
    const float4* base4 = (const float4*)(kc + (size_t)p * PAGE * 1024) + tid;
    float4 v0 = base4[0];
    float4 mx = v0, mn = v0;
#pragma unroll
    for (int t = 1; t < PAGE; ++t) {
        float4 v = base4[t * 256];
        mx.x = fmaxf(mx.x, v.x); mn.x = fminf(mn.x, v.x);
        mx.y = fmaxf(mx.y, v.y); mn.y = fminf(mn.y, v.y);
        mx.z = fmaxf(mx.z, v.z); mn.z = fminf(mn.z, v.z);
        mx.w = fmaxf(mx.w, v.w); mn.w = fminf(mn.w, v.w);
    }
    ((float4*)g_kmax)[p * 256 + tid] = mx;
    ((float4*)g_kmin)[p * 256 + tid] = mn;
}

// ======================== Quest score from stored min/max ========================
__global__ void score2_k(int np) {
    int tid = threadIdx.x;
    __shared__ float qs[HID];
    __shared__ float kmx[KV_HEADS * DIM];
    __shared__ float kmn[KV_HEADS * DIM];
    for (int i = tid; i < HID / 4; i += 256)
        ((float4*)qs)[i] = ((const float4*)g_qkv)[i];
#pragma unroll
    for (int pg = 0; pg < 16; ++pg) {
        int p = blockIdx.x * 16 + pg;              // block-uniform
        if (p == np - 1) {
            if (tid < H_HEADS) g_scores[tid * np + p] = INFINITY;
            continue;
        }
        ((float4*)kmx)[tid] = ((const float4*)g_kmax)[p * 256 + tid];
        ((float4*)kmn)[tid] = ((const float4*)g_kmin)[p * 256 + tid];
        __syncthreads();
        int h = tid >> 3, seg = tid & 7;
        int kv = h >> 2;
        float sum = 0.f;
        int db = seg * 16;
#pragma unroll
        for (int d = 0; d < 16; ++d) {
            float qv = qs[h * DIM + db + d];
            float km = kmx[kv * DIM + db + d];
            float kn = kmn[kv * DIM + db + d];
            sum += qv * (qv >= 0.f ? km : kn);
        }
        sum += __shfl_down_sync(0xffffffffu, sum, 4);
        sum += __shfl_down_sync(0xffffffffu, sum, 2);
        sum += __shfl_down_sync(0xffffffffu, sum, 1);
        if (seg == 0) g_scores[h * np + p] = sum;
        __syncthreads();
    }
}

// ======================== exact top-k: radix select, warp-shuffle scan ========================
__global__ void topk_k(int np) {
    int h = blockIdx.x;
    int tid = threadIdx.x;                 // 512 threads
    __shared__ unsigned su[MAXPAGES];
    __shared__ int      ties[64];
    __shared__ unsigned hist[256];
    __shared__ unsigned bcast[2];
    __shared__ unsigned cnt_gt, tie_cnt;

    for (int i = tid; i < np; i += 512) {
        float f = g_scores[h * np + i];
        unsigned u = __float_as_uint(f);
        su[i] = (u & 0x80000000u) ? ~u : (u | 0x80000000u);
    }
    if (tid == 0) { cnt_gt = 0; tie_cnt = 0; }
    __syncthreads();

    unsigned prefix = 0, R = TOPK;
#pragma unroll
    for (int level = 0; level < 4; ++level) {
        int shift = 24 - level * 8;
        unsigned mask = (level == 0) ? 0u : (0xFFFFFFFFu << (32 - level * 8));
        if (tid < 256) hist[tid] = 0;
        __syncthreads();
        for (int i = tid; i < np; i += 512) {
            unsigned u = su[i];
            if ((u & mask) == prefix) atomicAdd(&hist[(u >> shift) & 0xFF], 1u);
        }
        __syncthreads();
        if (tid < 32) {                      // warp 0: suffix scan of 256 bins
            int lane = tid;
            unsigned hb[8];
            unsigned lane_sum = 0;
#pragma unroll
            for (int b = 0; b < 8; ++b) { hb[b] = hist[lane * 8 + b]; lane_sum += hb[b]; }
            unsigned suf = lane_sum;
#pragma unroll
            for (int off = 1; off < 32; off <<= 1) {
                unsigned v = __shfl_down_sync(0xffffffffu, suf, off);
                if (lane + off < 32) suf += v;
            }
            unsigned tail = suf - lane_sum;  // sum of bins owned by lanes > lane
            unsigned cum = 0;
#pragma unroll
            for (int b = 7; b >= 0; --b) {
                cum += hb[b];
                unsigned incl = tail + cum;  // count of keys >= this bin (within prefix)
                unsigned gt = incl - hb[b];  // strictly greater
                if (gt < R && incl >= R) { bcast[0] = (unsigned)(lane * 8 + b); bcast[1] = R - gt; }
            }
        }
        __syncthreads();
        prefix |= (bcast[0] << shift);
        R = bcast[1];
        __syncthreads();
    }
    unsigned T = prefix, Rtie = R;

    for (int i = tid; i < np; i += 512) {
        unsigned u = su[i];
        if (u > T) {
            unsigned pos = atomicAdd(&cnt_gt, 1u);
            g_topk[h * TOPK + pos] = i;
        } else if (u == T) {
            unsigned tp = atomicAdd(&tie_cnt, 1u);
            if (tp < 64) ties[tp] = i;
        }
    }
    __syncthreads();

    int tcnt = (int)tie_cnt; if (tcnt > 64) tcnt = 64;
    if (tcnt > 1 && tid < 64) {
        for (int ph = 0; ph < tcnt; ++ph) {
            int i0 = 2 * tid + (ph & 1);
            if (i0 + 1 < tcnt) {
                int x0 = ties[i0], x1 = ties[i0 + 1];
                if (x0 > x1) { ties[i0] = x1; ties[i0 + 1] = x0; }
            }
            __syncwarp(0xffffffffu);
        }
    }
    __syncthreads();
    unsigned base = cnt_gt;                  // == TOPK - Rtie
    if (tid < Rtie) g_topk[h * TOPK + base + tid] = ties[tid];
}

// ======================== flash-decode partial ========================
__global__ void attn_partial_k(const float* __restrict__ kc, const float* __restrict__ vc,
                               int past) {
    int b = blockIdx.x;
    int h = b >> 5, chunk = b & 31;
    int kv = h >> 2;
    int tid = threadIdx.x, w = tid >> 5, lane = tid & 31;
    __shared__ float sc[TPC];
    __shared__ float redm[8];
    __shared__ float redl[8];
    __shared__ float accbuf[8 * DIM];

    const int* tk = g_topk + h * TOPK + chunk * PPC;   // 8 pages = 128 tokens

    {
        int sub = lane & 3, tg = lane >> 2;
        float4 q4[8];
        const float4* qp = (const float4*)(g_qkv + h * DIM);
#pragma unroll
        for (int m = 0; m < 8; ++m) q4[m] = qp[sub + 4 * m];
#pragma unroll
        for (int t = 0; t < 2; ++t) {
            int tw = w * 16 + t * 8 + tg;
            int page = tk[tw >> 4];
            int tok = page * PAGE + (tw & 15);
            const float4* kp = (tok == past)
                ? (const float4*)(g_qkv + 4096 + kv * DIM)
                : (const float4*)(kc + ((size_t)tok * KV_HEADS + kv) * DIM);
            float d = 0.f;
#pragma unroll
            for (int m = 0; m < 8; ++m) {
                float4 k4 = kp[sub + 4 * m];
                d = fmaf(q4[m].x, k4.x, d); d = fmaf(q4[m].y, k4.y, d);
                d = fmaf(q4[m].z, k4.z, d); d = fmaf(q4[m].w, k4.w, d);
            }
            d += __shfl_xor_sync(0xffffffffu, d, 1);
            d += __shfl_xor_sync(0xffffffffu, d, 2);
            if (sub == 0) sc[tw] = d * 0.08838834764831844f;   // 1/sqrt(128)
        }
    }
    __syncthreads();

    float v = (tid < TPC) ? sc[tid] : -INFINITY;
    float m = v;
#pragma unroll
    for (int o = 16; o; o >>= 1) m = fmaxf(m, __shfl_xor_sync(0xffffffffu, m, o));
    if (lane == 0) redm[w] = m;
    __syncthreads();
    if (tid == 0) {
        float mm = redm[0];
#pragma unroll
        for (int i = 1; i < 8; ++i) mm = fmaxf(mm, redm[i]);
        redm[0] = mm;
    }
    __syncthreads();
    float bm = redm[0];

    float e = (tid < TPC) ? __expf(v - bm) : 0.f;
    if (tid < TPC) sc[tid] = e;
    float l = e;
#pragma unroll
    for (int o = 16; o; o >>= 1) l += __shfl_xor_sync(0xffffffffu, l, o);
    if (lane == 0) redl[w] = l;
    __syncthreads();

    float4 acc = make_float4(0.f, 0.f, 0.f, 0.f);
#pragma unroll 4
    for (int s = 0; s < 16; ++s) {
        int tw = w * 16 + s;
        int page = tk[tw >> 4];
        int tok = page * PAGE + (tw & 15);
        const float4* vp = (tok == past)
            ? (const float4*)(g_qkv + 5120 + kv * DIM)
            : (const float4*)(vc + ((size_t)tok * KV_HEADS + kv) * DIM);
        float4 v4 = vp[lane];
        float ee = sc[tw];
        acc.x = fmaf(ee, v4.x, acc.x); acc.y = fmaf(ee, v4.y, acc.y);
        acc.z = fmaf(ee, v4.z, acc.z); acc.w = fmaf(ee, v4.w, acc.w);
    }
    *(float4*)(accbuf + w * DIM + lane * 4) = acc;
    __syncthreads();
    if (tid < DIM) {
        float s = 0.f;
#pragma unroll
        for (int ww = 0; ww < 8; ++ww) s += accbuf[ww * DIM + tid];
        g_acc[(h * NCHUNK + chunk) * DIM + tid] = s;
    }
    if (tid == 0) {
        float L = 0.f;
#pragma unroll
        for (int i = 0; i < 8; ++i) L += redl[i];
        g_m[h * NCHUNK + chunk] = bm;
        g_l[h * NCHUNK + chunk] = L;
    }
}

// ======================== launcher (graph fork: minmax ∥ GEMV chain) ========================
extern "C" void kernel_launch(void* const* d_in, const int* in_sizes, int n_in,
                              void* d_out, int out_size) {
    const float* x  = (const float*)d_in[0];
    const float* kc = (const float*)d_in[1];
    const float* vc = (const float*)d_in[2];
    const float* Wq = (const float*)d_in[3];
    const float* Wk = (const float*)d_in[4];
    const float* Wv = (const float*)d_in[5];
    const float* Wo = (const float*)d_in[6];
    float* out = (float*)d_out;

    int past = in_sizes[1] / (KV_HEADS * DIM);   // 32767
    int np   = (past + 1) / PAGE;                // 2048

    // fork: side stream scans k_cache min/max while main stream does QKV GEMV
    cudaEventRecord(s_evFork, 0);
    cudaStreamWaitEvent(s_side, s_evFork, 0);
    minmax_k<<<np, 256, 0, s_side>>>(kc);

    gemv_qkv_k<<<768, 256>>>(Wq, Wk, Wv, x);
    reduce_rope_k<<<QKV_N / 256, 256>>>(past);

    // join
    cudaEventRecord(s_evJoin, s_side);
    cudaStreamWaitEvent(0, s_evJoin, 0);

    score2_k<<<np / 16, 256>>>(np);
    topk_k<<<H_HEADS, 512>>>(np);
    attn_partial_k<<<H_HEADS * NCHUNK, 256>>>(kc, vc, past);
    gemv_o_k<<<512, 256>>>(Wo);
    reduce_out_k<<<HID / 256, 256>>>(out);
}

// round 8
// speedup vs baseline: 1.0717x; 1.0717x over previous
#include <cuda_runtime.h>
#include <cuda_bf16.h>
#include <math.h>
#include <stdint.h>

#define H_HEADS   32
#define KV_HEADS  8
#define DIM       128
#define PAGE      16
#define TOPK      256
#define HID       4096
#define QKV_N     6144         // 4096 q + 1024 k + 1024 v
#define SPLIT     128          // K-chunks of 32 rows
#define MAXPAGES  2048
#define NCHUNK    32           // flash-decode chunks per head
#define PPC       8            // pages per chunk
#define TPC       128          // tokens per chunk

extern "C" __device__ float __nv_powf(float, float);

// -------- device scratch (symbols only referenced inside kernels!) --------
__device__ float g_partial[SPLIT * QKV_N];
__device__ float g_qkv[QKV_N];                 // [0,4096)=q, [4096,5120)=k, [5120,6144)=v
__device__ float g_kmax[MAXPAGES * KV_HEADS * DIM];   // 8MB
__device__ float g_kmin[MAXPAGES * KV_HEADS * DIM];   // 8MB
__device__ float g_scores[H_HEADS * MAXPAGES];
__device__ int   g_topk[H_HEADS * TOPK];
__device__ float g_m[H_HEADS * NCHUNK];
__device__ float g_l[H_HEADS * NCHUNK];
__device__ float g_acc[H_HEADS * NCHUNK * DIM];

// -------- streams/events for graph fork (created once, before any capture) --------
static cudaStream_t s_side;
static cudaEvent_t  s_evFork, s_evJoin;
static struct StreamInit {
    StreamInit() {
        cudaStreamCreateWithFlags(&s_side, cudaStreamNonBlocking);
        cudaEventCreateWithFlags(&s_evFork, cudaEventDisableTiming);
        cudaEventCreateWithFlags(&s_evJoin, cudaEventDisableTiming);
    }
} s_streamInit;

// ======================== fused QKV split-K GEMV (float4) ========================
__global__ void gemv_qkv_k(const float* __restrict__ Wq, const float* __restrict__ Wk,
                           const float* __restrict__ Wv, const float* __restrict__ x) {
    int b = blockIdx.x, tid = threadIdx.x;
    const float* W; int N4, xb, chunk, colOff4;
    if (b < 512)      { W = Wq; N4 = 1024; xb = b & 3; chunk = b >> 2;  colOff4 = 0; }
    else if (b < 640) { W = Wk; N4 = 256;  xb = 0;     chunk = b - 512; colOff4 = 1024; }
    else              { W = Wv; N4 = 256;  xb = 0;     chunk = b - 640; colOff4 = 1280; }
    __shared__ float xs[32];
    if (tid < 32) xs[tid] = x[chunk * 32 + tid];
    __syncthreads();
    int j4 = xb * 256 + tid;
    const float4* w4 = (const float4*)W + (size_t)(chunk * 32) * N4 + j4;
    float4 a = make_float4(0.f, 0.f, 0.f, 0.f);
#pragma unroll
    for (int i = 0; i < 32; ++i) {
        float4 wv = w4[(size_t)i * N4];
        float xv = xs[i];
        a.x = fmaf(xv, wv.x, a.x); a.y = fmaf(xv, wv.y, a.y);
        a.z = fmaf(xv, wv.z, a.z); a.w = fmaf(xv, wv.w, a.w);
    }
    ((float4*)g_partial)[chunk * (QKV_N / 4) + colOff4 + j4] = a;
}

// ======================== Wo GEMV with fused flash-decode combine ========================
__global__ void gemv_o_k(const float* __restrict__ Wo) {
    int b = blockIdx.x, tid = threadIdx.x;
    int xb = b & 3, chunk = b >> 2;          // chunk in [0,128)
    __shared__ float xs[32];
    if (tid < 32) {
        int h = chunk >> 2;                  // 4 chunks (32 dims each) per head
        int d = (chunk & 3) * 32 + tid;
        float M = -INFINITY;
#pragma unroll
        for (int c = 0; c < NCHUNK; ++c) M = fmaxf(M, g_m[h * NCHUNK + c]);
        float L = 0.f, acc = 0.f;
#pragma unroll
        for (int c = 0; c < NCHUNK; ++c) {
            float f = __expf(g_m[h * NCHUNK + c] - M);
            L += f * g_l[h * NCHUNK + c];
            acc += f * g_acc[(h * NCHUNK + c) * DIM + d];
        }
        xs[tid] = acc / L;
    }
    __syncthreads();
    int j4 = xb * 256 + tid;
    const float4* w4 = (const float4*)Wo + (size_t)(chunk * 32) * 1024 + j4;
    float4 a = make_float4(0.f, 0.f, 0.f, 0.f);
#pragma unroll
    for (int i = 0; i < 32; ++i) {
        float4 wv = w4[(size_t)i * 1024];
        float xv = xs[i];
        a.x = fmaf(xv, wv.x, a.x); a.y = fmaf(xv, wv.y, a.y);
        a.z = fmaf(xv, wv.z, a.z); a.w = fmaf(xv, wv.w, a.w);
    }
    ((float4*)g_partial)[chunk * (QKV_N / 4) + j4] = a;
}

// ======================== reduce partials + fused RoPE ========================
__global__ void reduce_rope_k(int past) {
    int tid = threadIdx.x;
    int e = blockIdx.x * 256 + tid;
    __shared__ float redsum[256];
    __shared__ float ctab[64], stab[64];
    if (tid < 64) {
        float ee = (float)tid / 64.0f;
        float p = __nv_powf(10000.0f, ee);
        float invf = 1.0f / p;
        float ang = (float)past * invf;
        double aa = (double)ang;
        ctab[tid] = (float)cos(aa);
        stab[tid] = (float)sin(aa);
    }
    float s = 0.f;
#pragma unroll 16
    for (int c = 0; c < SPLIT; ++c) s += g_partial[c * QKV_N + e];
    redsum[tid] = s;
    __syncthreads();
    int row = e >> 7, col = e & 127;
    float outv = s;
    if (row < 40) {                       // q rows 0-31, k rows 32-39
        float partner = redsum[tid ^ 64];
        float c = ctab[col & 63], sn = stab[col & 63];
        outv = (col < 64) ? (s * c - partner * sn) : (s * c + partner * sn);
    }
    g_qkv[e] = outv;
}

__global__ void reduce_out_k(float* __restrict__ out) {
    int j = blockIdx.x * 256 + threadIdx.x;
    float s = 0.f;
#pragma unroll 16
    for (int c = 0; c < SPLIT; ++c) s += g_partial[c * QKV_N + j];
    out[j] = s;
}

// ======================== page min/max scan (q-independent, side stream) ========
__global__ void minmax_k(const float* __restrict__ kc) {
    int p = blockIdx.x;
    int tid = threadIdx.x;
    const float4* base4 = (const float4*)(kc + (size_t)p * PAGE * 1024) + tid;
    float4 v0 = base4[0];
    float4 mx = v0, mn = v0;
#pragma unroll
    for (int t = 1; t < PAGE; ++t) {
        float4 v = base4[t * 256];
        mx.x = fmaxf(mx.x, v.x); mn.x = fminf(mn.x, v.x);
        mx.y = fmaxf(mx.y, v.y); mn.y = fminf(mn.y, v.y);
        mx.z = fmaxf(mx.z, v.z); mn.z = fminf(mn.z, v.z);
        mx.w = fmaxf(mx.w, v.w); mn.w = fminf(mn.w, v.w);
    }
    ((float4*)g_kmax)[p * 256 + tid] = mx;
    ((float4*)g_kmin)[p * 256 + tid] = mn;
}

// ======================== Quest score from stored min/max (1 page/block) ========
__global__ void score2_k(int np) {
    int p = blockIdx.x;
    int tid = threadIdx.x;
    if (p == np - 1) {
        if (tid < H_HEADS) g_scores[tid * np + p] = INFINITY;
        return;
    }
    __shared__ float qs[HID];
    __shared__ float kmx[KV_HEADS * DIM];
    __shared__ float kmn[KV_HEADS * DIM];
#pragma unroll
    for (int i = 0; i < 4; ++i)
        ((float4*)qs)[i * 256 + tid] = ((const float4*)g_qkv)[i * 256 + tid];
    ((float4*)kmx)[tid] = ((const float4*)g_kmax)[p * 256 + tid];
    ((float4*)kmn)[tid] = ((const float4*)g_kmin)[p * 256 + tid];
    __syncthreads();
    int h = tid >> 3, seg = tid & 7;
    int kv = h >> 2;
    float sum = 0.f;
    int db = seg * 16;
#pragma unroll
    for (int d = 0; d < 16; ++d) {
        float qv = qs[h * DIM + db + d];
        float km = kmx[kv * DIM + db + d];
        float kn = kmn[kv * DIM + db + d];
        sum += qv * (qv >= 0.f ? km : kn);
    }
    sum += __shfl_down_sync(0xffffffffu, sum, 4);
    sum += __shfl_down_sync(0xffffffffu, sum, 2);
    sum += __shfl_down_sync(0xffffffffu, sum, 1);
    if (seg == 0) g_scores[h * np + p] = sum;
}

// ======================== exact top-k: radix select, warp-shuffle scan ========================
__global__ void topk_k(int np) {
    int h = blockIdx.x;
    int tid = threadIdx.x;                 // 512 threads
    __shared__ unsigned su[MAXPAGES];
    __shared__ int      ties[64];
    __shared__ unsigned hist[256];
    __shared__ unsigned bcast[2];
    __shared__ unsigned cnt_gt, tie_cnt;

    for (int i = tid; i < np; i += 512) {
        float f = g_scores[h * np + i];
        unsigned u = __float_as_uint(f);
        su[i] = (u & 0x80000000u) ? ~u : (u | 0x80000000u);
    }
    if (tid == 0) { cnt_gt = 0; tie_cnt = 0; }
    __syncthreads();

    unsigned prefix = 0, R = TOPK;
#pragma unroll
    for (int level = 0; level < 4; ++level) {
        int shift = 24 - level * 8;
        unsigned mask = (level == 0) ? 0u : (0xFFFFFFFFu << (32 - level * 8));
        if (tid < 256) hist[tid] = 0;
        __syncthreads();
        for (int i = tid; i < np; i += 512) {
            unsigned u = su[i];
            if ((u & mask) == prefix) atomicAdd(&hist[(u >> shift) & 0xFF], 1u);
        }
        __syncthreads();
        if (tid < 32) {                      // warp 0: suffix scan of 256 bins
            int lane = tid;
            unsigned hb[8];
            unsigned lane_sum = 0;
#pragma unroll
            for (int b = 0; b < 8; ++b) { hb[b] = hist[lane * 8 + b]; lane_sum += hb[b]; }
            unsigned suf = lane_sum;
#pragma unroll
            for (int off = 1; off < 32; off <<= 1) {
                unsigned v = __shfl_down_sync(0xffffffffu, suf, off);
                if (lane + off < 32) suf += v;
            }
            unsigned tail = suf - lane_sum;  // sum of bins owned by lanes > lane
            unsigned cum = 0;
#pragma unroll
            for (int b = 7; b >= 0; --b) {
                cum += hb[b];
                unsigned incl = tail + cum;  // count of keys >= this bin (within prefix)
                unsigned gt = incl - hb[b];  // strictly greater
                if (gt < R && incl >= R) { bcast[0] = (unsigned)(lane * 8 + b); bcast[1] = R - gt; }
            }
        }
        __syncthreads();
        prefix |= (bcast[0] << shift);
        R = bcast[1];
        __syncthreads();
    }
    unsigned T = prefix, Rtie = R;

    for (int i = tid; i < np; i += 512) {
        unsigned u = su[i];
        if (u > T) {
            unsigned pos = atomicAdd(&cnt_gt, 1u);
            g_topk[h * TOPK + pos] = i;
        } else if (u == T) {
            unsigned tp = atomicAdd(&tie_cnt, 1u);
            if (tp < 64) ties[tp] = i;
        }
    }
    __syncthreads();

    int tcnt = (int)tie_cnt; if (tcnt > 64) tcnt = 64;
    if (tcnt > 1 && tid < 64) {
        for (int ph = 0; ph < tcnt; ++ph) {
            int i0 = 2 * tid + (ph & 1);
            if (i0 + 1 < tcnt) {
                int x0 = ties[i0], x1 = ties[i0 + 1];
                if (x0 > x1) { ties[i0] = x1; ties[i0 + 1] = x0; }
            }
            __syncwarp(0xffffffffu);
        }
    }
    __syncthreads();
    unsigned base = cnt_gt;                  // == TOPK - Rtie
    if (tid < Rtie) g_topk[h * TOPK + base + tid] = ties[tid];
}

// ======================== flash-decode partial ========================
__global__ void attn_partial_k(const float* __restrict__ kc, const float* __restrict__ vc,
                               int past) {
    int b = blockIdx.x;
    int h = b >> 5, chunk = b & 31;
    int kv = h >> 2;
    int tid = threadIdx.x, w = tid >> 5, lane = tid & 31;
    __shared__ float sc[TPC];
    __shared__ float redm[8];
    __shared__ float redl[8];
    __shared__ float accbuf[8 * DIM];

    const int* tk = g_topk + h * TOPK + chunk * PPC;   // 8 pages = 128 tokens

    {
        int sub = lane & 3, tg = lane >> 2;
        float4 q4[8];
        const float4* qp = (const float4*)(g_qkv + h * DIM);
#pragma unroll
        for (int m = 0; m < 8; ++m) q4[m] = qp[sub + 4 * m];
#pragma unroll
        for (int t = 0; t < 2; ++t) {
            int tw = w * 16 + t * 8 + tg;
            int page = tk[tw >> 4];
            int tok = page * PAGE + (tw & 15);
            const float4* kp = (tok == past)
                ? (const float4*)(g_qkv + 4096 + kv * DIM)
                : (const float4*)(kc + ((size_t)tok * KV_HEADS + kv) * DIM);
            float d = 0.f;
#pragma unroll
            for (int m = 0; m < 8; ++m) {
                float4 k4 = kp[sub + 4 * m];
                d = fmaf(q4[m].x, k4.x, d); d = fmaf(q4[m].y, k4.y, d);
                d = fmaf(q4[m].z, k4.z, d); d = fmaf(q4[m].w, k4.w, d);
            }
            d += __shfl_xor_sync(0xffffffffu, d, 1);
            d += __shfl_xor_sync(0xffffffffu, d, 2);
            if (sub == 0) sc[tw] = d * 0.08838834764831844f;   // 1/sqrt(128)
        }
    }
    __syncthreads();

    float v = (tid < TPC) ? sc[tid] : -INFINITY;
    float m = v;
#pragma unroll
    for (int o = 16; o; o >>= 1) m = fmaxf(m, __shfl_xor_sync(0xffffffffu, m, o));
    if (lane == 0) redm[w] = m;
    __syncthreads();
    if (tid == 0) {
        float mm = redm[0];
#pragma unroll
        for (int i = 1; i < 8; ++i) mm = fmaxf(mm, redm[i]);
        redm[0] = mm;
    }
    __syncthreads();
    float bm = redm[0];

    float e = (tid < TPC) ? __expf(v - bm) : 0.f;
    if (tid < TPC) sc[tid] = e;
    float l = e;
#pragma unroll
    for (int o = 16; o; o >>= 1) l += __shfl_xor_sync(0xffffffffu, l, o);
    if (lane == 0) redl[w] = l;
    __syncthreads();

    float4 acc = make_float4(0.f, 0.f, 0.f, 0.f);
#pragma unroll 4
    for (int s = 0; s < 16; ++s) {
        int tw = w * 16 + s;
        int page = tk[tw >> 4];
        int tok = page * PAGE + (tw & 15);
        const float4* vp = (tok == past)
            ? (const float4*)(g_qkv + 5120 + kv * DIM)
            : (const float4*)(vc + ((size_t)tok * KV_HEADS + kv) * DIM);
        float4 v4 = vp[lane];
        float ee = sc[tw];
        acc.x = fmaf(ee, v4.x, acc.x); acc.y = fmaf(ee, v4.y, acc.y);
        acc.z = fmaf(ee, v4.z, acc.z); acc.w = fmaf(ee, v4.w, acc.w);
    }
    *(float4*)(accbuf + w * DIM + lane * 4) = acc;
    __syncthreads();
    if (tid < DIM) {
        float s = 0.f;
#pragma unroll
        for (int ww = 0; ww < 8; ++ww) s += accbuf[ww * DIM + tid];
        g_acc[(h * NCHUNK + chunk) * DIM + tid] = s;
    }
    if (tid == 0) {
        float L = 0.f;
#pragma unroll
        for (int i = 0; i < 8; ++i) L += redl[i];
        g_m[h * NCHUNK + chunk] = bm;
        g_l[h * NCHUNK + chunk] = L;
    }
}

// ======================== launcher (graph fork: minmax ∥ GEMV chain) ========================
extern "C" void kernel_launch(void* const* d_in, const int* in_sizes, int n_in,
                              void* d_out, int out_size) {
    const float* x  = (const float*)d_in[0];
    const float* kc = (const float*)d_in[1];
    const float* vc = (const float*)d_in[2];
    const float* Wq = (const float*)d_in[3];
    const float* Wk = (const float*)d_in[4];
    const float* Wv = (const float*)d_in[5];
    const float* Wo = (const float*)d_in[6];
    float* out = (float*)d_out;

    int past = in_sizes[1] / (KV_HEADS * DIM);   // 32767
    int np   = (past + 1) / PAGE;                // 2048

    // fork: side stream scans k_cache min/max while main stream does QKV GEMV
    cudaEventRecord(s_evFork, 0);
    cudaStreamWaitEvent(s_side, s_evFork, 0);
    minmax_k<<<np, 256, 0, s_side>>>(kc);

    gemv_qkv_k<<<768, 256>>>(Wq, Wk, Wv, x);
    reduce_rope_k<<<QKV_N / 256, 256>>>(past);

    // join
    cudaEventRecord(s_evJoin, s_side);
    cudaStreamWaitEvent(0, s_evJoin, 0);

    score2_k<<<np, 256>>>(np);
    topk_k<<<H_HEADS, 512>>>(np);
    attn_partial_k<<<H_HEADS * NCHUNK, 256>>>(kc, vc, past);
    gemv_o_k<<<512, 256>>>(Wo);
    reduce_out_k<<<HID / 256, 256>>>(out);
}

// round 9
// speedup vs baseline: 1.2030x; 1.1226x over previous
#include <cuda_runtime.h>
#include <cuda_bf16.h>
#include <math.h>
#include <stdint.h>

#define H_HEADS   32
#define KV_HEADS  8
#define DIM       128
#define PAGE      16
#define TOPK      256
#define HID       4096
#define QKV_N     6144         // 4096 q + 1024 k + 1024 v
#define SPLIT     128          // K-chunks of 32 rows
#define MAXPAGES  2048
#define NCHUNK    32           // flash-decode chunks per head
#define PPC       8            // pages per chunk
#define TPC       128          // tokens per chunk

extern "C" __device__ float __nv_powf(float, float);

// -------- device scratch (symbols only referenced inside kernels!) --------
__device__ float g_partial[SPLIT * QKV_N];
__device__ float g_qkv[QKV_N];                 // [0,4096)=q, [4096,5120)=k, [5120,6144)=v
__device__ float g_scores[H_HEADS * MAXPAGES];
__device__ int   g_topk[H_HEADS * TOPK];
__device__ float g_m[H_HEADS * NCHUNK];
__device__ float g_l[H_HEADS * NCHUNK];
__device__ float g_acc[H_HEADS * NCHUNK * DIM];

// ======================== fused QKV split-K GEMV (float4) ========================
__global__ void gemv_qkv_k(const float* __restrict__ Wq, const float* __restrict__ Wk,
                           const float* __restrict__ Wv, const float* __restrict__ x) {
    int b = blockIdx.x, tid = threadIdx.x;
    const float* W; int N4, xb, chunk, colOff4;
    if (b < 512)      { W = Wq; N4 = 1024; xb = b & 3; chunk = b >> 2;  colOff4 = 0; }
    else if (b < 640) { W = Wk; N4 = 256;  xb = 0;     chunk = b - 512; colOff4 = 1024; }
    else              { W = Wv; N4 = 256;  xb = 0;     chunk = b - 640; colOff4 = 1280; }
    __shared__ float xs[32];
    if (tid < 32) xs[tid] = x[chunk * 32 + tid];
    __syncthreads();
    int j4 = xb * 256 + tid;
    const float4* w4 = (const float4*)W + (size_t)(chunk * 32) * N4 + j4;
    float4 a = make_float4(0.f, 0.f, 0.f, 0.f);
#pragma unroll
    for (int i = 0; i < 32; ++i) {
        float4 wv = w4[(size_t)i * N4];
        float xv = xs[i];
        a.x = fmaf(xv, wv.x, a.x); a.y = fmaf(xv, wv.y, a.y);
        a.z = fmaf(xv, wv.z, a.z); a.w = fmaf(xv, wv.w, a.w);
    }
    ((float4*)g_partial)[chunk * (QKV_N / 4) + colOff4 + j4] = a;
}

// ======================== Wo GEMV with fused flash-decode combine ========================
__global__ void gemv_o_k(const float* __restrict__ Wo) {
    int b = blockIdx.x, tid = threadIdx.x;
    int xb = b & 3, chunk = b >> 2;          // chunk in [0,128)
    __shared__ float xs[32];
    if (tid < 32) {
        int h = chunk >> 2;                  // 4 chunks (32 dims each) per head
        int d = (chunk & 3) * 32 + tid;
        float M = -INFINITY;
#pragma unroll
        for (int c = 0; c < NCHUNK; ++c) M = fmaxf(M, g_m[h * NCHUNK + c]);
        float L = 0.f, acc = 0.f;
#pragma unroll
        for (int c = 0; c < NCHUNK; ++c) {
            float f = __expf(g_m[h * NCHUNK + c] - M);
            L += f * g_l[h * NCHUNK + c];
            acc += f * g_acc[(h * NCHUNK + c) * DIM + d];
        }
        xs[tid] = acc / L;
    }
    __syncthreads();
    int j4 = xb * 256 + tid;
    const float4* w4 = (const float4*)Wo + (size_t)(chunk * 32) * 1024 + j4;
    float4 a = make_float4(0.f, 0.f, 0.f, 0.f);
#pragma unroll
    for (int i = 0; i < 32; ++i) {
        float4 wv = w4[(size_t)i * 1024];
        float xv = xs[i];
        a.x = fmaf(xv, wv.x, a.x); a.y = fmaf(xv, wv.y, a.y);
        a.z = fmaf(xv, wv.z, a.z); a.w = fmaf(xv, wv.w, a.w);
    }
    ((float4*)g_partial)[chunk * (QKV_N / 4) + j4] = a;
}

// ======================== reduce partials + fused RoPE ========================
__global__ void reduce_rope_k(int past) {
    int tid = threadIdx.x;
    int e = blockIdx.x * 256 + tid;
    __shared__ float redsum[256];
    __shared__ float ctab[64], stab[64];
    if (tid < 64) {
        float ee = (float)tid / 64.0f;
        float p = __nv_powf(10000.0f, ee);
        float invf = 1.0f / p;
        float ang = (float)past * invf;
        double aa = (double)ang;
        ctab[tid] = (float)cos(aa);
        stab[tid] = (float)sin(aa);
    }
    float s = 0.f;
#pragma unroll 16
    for (int c = 0; c < SPLIT; ++c) s += g_partial[c * QKV_N + e];
    redsum[tid] = s;
    __syncthreads();
    int row = e >> 7, col = e & 127;
    float outv = s;
    if (row < 40) {                       // q rows 0-31, k rows 32-39
        float partner = redsum[tid ^ 64];
        float c = ctab[col & 63], sn = stab[col & 63];
        outv = (col < 64) ? (s * c - partner * sn) : (s * c + partner * sn);
    }
    g_qkv[e] = outv;
}

__global__ void reduce_out_k(float* __restrict__ out) {
    int j = blockIdx.x * 256 + threadIdx.x;
    float s = 0.f;
#pragma unroll 16
    for (int c = 0; c < SPLIT; ++c) s += g_partial[c * QKV_N + j];
    out[j] = s;
}

// ======================== page min/max + Quest score (4 pages/block, fused) ========
__global__ void score_k(const float* __restrict__ kc, int np) {
    int tid = threadIdx.x;
    __shared__ float qs[HID];
    __shared__ float kmx[KV_HEADS * DIM];
    __shared__ float kmn[KV_HEADS * DIM];
    for (int i = tid; i < HID / 4; i += 256)
        ((float4*)qs)[i] = ((const float4*)g_qkv)[i];
#pragma unroll
    for (int pg = 0; pg < 4; ++pg) {
        int p = blockIdx.x * 4 + pg;               // block-uniform
        if (p == np - 1) {
            if (tid < H_HEADS) g_scores[tid * np + p] = INFINITY;
            continue;
        }
        {
            const float4* base4 = (const float4*)(kc + (size_t)p * PAGE * 1024) + tid;
            float4 v0 = base4[0];
            float4 mx = v0, mn = v0;
#pragma unroll
            for (int t = 1; t < PAGE; ++t) {
                float4 v = base4[t * 256];
                mx.x = fmaxf(mx.x, v.x); mn.x = fminf(mn.x, v.x);
                mx.y = fmaxf(mx.y, v.y); mn.y = fminf(mn.y, v.y);
                mx.z = fmaxf(mx.z, v.z); mn.z = fminf(mn.z, v.z);
                mx.w = fmaxf(mx.w, v.w); mn.w = fminf(mn.w, v.w);
            }
            ((float4*)kmx)[tid] = mx;
            ((float4*)kmn)[tid] = mn;
        }
        __syncthreads();                           // minmax (and qs on pg 0) ready
        int h = tid >> 3, seg = tid & 7;
        int kv = h >> 2;
        float sum = 0.f;
        int db = seg * 16;
#pragma unroll
        for (int d = 0; d < 16; ++d) {
            float qv = qs[h * DIM + db + d];
            float km = kmx[kv * DIM + db + d];
            float kn = kmn[kv * DIM + db + d];
            sum += qv * (qv >= 0.f ? km : kn);
        }
        sum += __shfl_down_sync(0xffffffffu, sum, 4);
        sum += __shfl_down_sync(0xffffffffu, sum, 2);
        sum += __shfl_down_sync(0xffffffffu, sum, 1);
        if (seg == 0) g_scores[h * np + p] = sum;
        __syncthreads();                           // before next page overwrites kmx/kmn
    }
}

// ======================== exact top-k: radix select, warp-shuffle scan ========================
__global__ void topk_k(int np) {
    int h = blockIdx.x;
    int tid = threadIdx.x;                 // 512 threads
    __shared__ unsigned su[MAXPAGES];
    __shared__ int      ties[64];
    __shared__ unsigned hist[256];
    __shared__ unsigned bcast[2];
    __shared__ unsigned cnt_gt, tie_cnt;

    for (int i = tid; i < np; i += 512) {
        float f = g_scores[h * np + i];
        unsigned u = __float_as_uint(f);
        su[i] = (u & 0x80000000u) ? ~u : (u | 0x80000000u);
    }
    if (tid == 0) { cnt_gt = 0; tie_cnt = 0; }
    __syncthreads();

    unsigned prefix = 0, R = TOPK;
#pragma unroll
    for (int level = 0; level < 4; ++level) {
        int shift = 24 - level * 8;
        unsigned mask = (level == 0) ? 0u : (0xFFFFFFFFu << (32 - level * 8));
        if (tid < 256) hist[tid] = 0;
        __syncthreads();
        for (int i = tid; i < np; i += 512) {
            unsigned u = su[i];
            if ((u & mask) == prefix) atomicAdd(&hist[(u >> shift) & 0xFF], 1u);
        }
        __syncthreads();
        if (tid < 32) {                      // warp 0: suffix scan of 256 bins
            int lane = tid;
            unsigned hb[8];
            unsigned lane_sum = 0;
#pragma unroll
            for (int b = 0; b < 8; ++b) { hb[b] = hist[lane * 8 + b]; lane_sum += hb[b]; }
            unsigned suf = lane_sum;
#pragma unroll
            for (int off = 1; off < 32; off <<= 1) {
                unsigned v = __shfl_down_sync(0xffffffffu, suf, off);
                if (lane + off < 32) suf += v;
            }
            unsigned tail = suf - lane_sum;  // sum of bins owned by lanes > lane
            unsigned cum = 0;
#pragma unroll
            for (int b = 7; b >= 0; --b) {
                cum += hb[b];
                unsigned incl = tail + cum;  // count of keys >= this bin (within prefix)
                unsigned gt = incl - hb[b];  // strictly greater
                if (gt < R && incl >= R) { bcast[0] = (unsigned)(lane * 8 + b); bcast[1] = R - gt; }
            }
        }
        __syncthreads();
        prefix |= (bcast[0] << shift);
        R = bcast[1];
        __syncthreads();
    }
    unsigned T = prefix, Rtie = R;

    for (int i = tid; i < np; i += 512) {
        unsigned u = su[i];
        if (u > T) {
            unsigned pos = atomicAdd(&cnt_gt, 1u);
            g_topk[h * TOPK + pos] = i;
        } else if (u == T) {
            unsigned tp = atomicAdd(&tie_cnt, 1u);
            if (tp < 64) ties[tp] = i;
        }
    }
    __syncthreads();

    int tcnt = (int)tie_cnt; if (tcnt > 64) tcnt = 64;
    if (tcnt > 1 && tid < 64) {
        for (int ph = 0; ph < tcnt; ++ph) {
            int i0 = 2 * tid + (ph & 1);
            if (i0 + 1 < tcnt) {
                int x0 = ties[i0], x1 = ties[i0 + 1];
                if (x0 > x1) { ties[i0] = x1; ties[i0 + 1] = x0; }
            }
            __syncwarp(0xffffffffu);
        }
    }
    __syncthreads();
    unsigned base = cnt_gt;                  // == TOPK - Rtie
    if (tid < Rtie) g_topk[h * TOPK + base + tid] = ties[tid];
}

// ======================== flash-decode partial (high-MLP) ========================
__global__ void attn_partial_k(const float* __restrict__ kc, const float* __restrict__ vc,
                               int past) {
    int b = blockIdx.x;
    int h = b >> 5, chunk = b & 31;
    int kv = h >> 2;
    int tid = threadIdx.x, w = tid >> 5, lane = tid & 31;
    __shared__ float sc[TPC];
    __shared__ float redm[8];
    __shared__ float redl[8];
    __shared__ float accbuf[8 * DIM];

    const int* tk = g_topk + h * TOPK + chunk * PPC;   // 8 pages = 128 tokens

    // ---- scores: warp w owns tokens [w*16, w*16+16); both token-groups' loads
    //      issued before any reduction (16 independent float4 loads per lane) ----
    {
        int sub = lane & 3, tg = lane >> 2;
        float4 q4[8];
        const float4* qp = (const float4*)(g_qkv + h * DIM);
#pragma unroll
        for (int m = 0; m < 8; ++m) q4[m] = qp[sub + 4 * m];

        const float4* kp[2];
        int tw0 = w * 16 + tg, tw1 = w * 16 + 8 + tg;
#pragma unroll
        for (int t = 0; t < 2; ++t) {
            int tw = t == 0 ? tw0 : tw1;
            int page = tk[tw >> 4];
            int tok = page * PAGE + (tw & 15);
            kp[t] = (tok == past)
                ? (const float4*)(g_qkv + 4096 + kv * DIM)
                : (const float4*)(kc + ((size_t)tok * KV_HEADS + kv) * DIM);
        }
        float4 k40[8], k41[8];
#pragma unroll
        for (int m = 0; m < 8; ++m) k40[m] = kp[0][sub + 4 * m];
#pragma unroll
        for (int m = 0; m < 8; ++m) k41[m] = kp[1][sub + 4 * m];

        float d0 = 0.f, d1 = 0.f;
#pragma unroll
        for (int m = 0; m < 8; ++m) {
            d0 = fmaf(q4[m].x, k40[m].x, d0); d0 = fmaf(q4[m].y, k40[m].y, d0);
            d0 = fmaf(q4[m].z, k40[m].z, d0); d0 = fmaf(q4[m].w, k40[m].w, d0);
            d1 = fmaf(q4[m].x, k41[m].x, d1); d1 = fmaf(q4[m].y, k41[m].y, d1);
            d1 = fmaf(q4[m].z, k41[m].z, d1); d1 = fmaf(q4[m].w, k41[m].w, d1);
        }
        d0 += __shfl_xor_sync(0xffffffffu, d0, 1);
        d0 += __shfl_xor_sync(0xffffffffu, d0, 2);
        d1 += __shfl_xor_sync(0xffffffffu, d1, 1);
        d1 += __shfl_xor_sync(0xffffffffu, d1, 2);
        if (sub == 0) {
            sc[tw0] = d0 * 0.08838834764831844f;   // 1/sqrt(128)
            sc[tw1] = d1 * 0.08838834764831844f;
        }
    }
    __syncthreads();

    float v = (tid < TPC) ? sc[tid] : -INFINITY;
    float m = v;
#pragma unroll
    for (int o = 16; o; o >>= 1) m = fmaxf(m, __shfl_xor_sync(0xffffffffu, m, o));
    if (lane == 0) redm[w] = m;
    __syncthreads();
    if (tid == 0) {
        float mm = redm[0];
#pragma unroll
        for (int i = 1; i < 8; ++i) mm = fmaxf(mm, redm[i]);
        redm[0] = mm;
    }
    __syncthreads();
    float bm = redm[0];

    float e = (tid < TPC) ? __expf(v - bm) : 0.f;
    if (tid < TPC) sc[tid] = e;
    float l = e;
#pragma unroll
    for (int o = 16; o; o >>= 1) l += __shfl_xor_sync(0xffffffffu, l, o);
    if (lane == 0) redl[w] = l;
    __syncthreads();

    // ---- V accumulate: full unroll -> 16 independent float4 loads in flight ----
    float4 acc = make_float4(0.f, 0.f, 0.f, 0.f);
#pragma unroll
    for (int s = 0; s < 16; ++s) {
        int tw = w * 16 + s;
        int page = tk[tw >> 4];
        int tok = page * PAGE + (tw & 15);
        const float4* vp = (tok == past)
            ? (const float4*)(g_qkv + 5120 + kv * DIM)
            : (const float4*)(vc + ((size_t)tok * KV_HEADS + kv) * DIM);
        float4 v4 = vp[lane];
        float ee = sc[tw];
        acc.x = fmaf(ee, v4.x, acc.x); acc.y = fmaf(ee, v4.y, acc.y);
        acc.z = fmaf(ee, v4.z, acc.z); acc.w = fmaf(ee, v4.w, acc.w);
    }
    *(float4*)(accbuf + w * DIM + lane * 4) = acc;
    __syncthreads();
    if (tid < DIM) {
        float s = 0.f;
#pragma unroll
        for (int ww = 0; ww < 8; ++ww) s += accbuf[ww * DIM + tid];
        g_acc[(h * NCHUNK + chunk) * DIM + tid] = s;
    }
    if (tid == 0) {
        float L = 0.f;
#pragma unroll
        for (int i = 0; i < 8; ++i) L += redl[i];
        g_m[h * NCHUNK + chunk] = bm;
        g_l[h * NCHUNK + chunk] = L;
    }
}

// ======================== launcher ========================
extern "C" void kernel_launch(void* const* d_in, const int* in_sizes, int n_in,
                              void* d_out, int out_size) {
    const float* x  = (const float*)d_in[0];
    const float* kc = (const float*)d_in[1];
    const float* vc = (const float*)d_in[2];
    const float* Wq = (const float*)d_in[3];
    const float* Wk = (const float*)d_in[4];
    const float* Wv = (const float*)d_in[5];
    const float* Wo = (const float*)d_in[6];
    float* out = (float*)d_out;

    int past = in_sizes[1] / (KV_HEADS * DIM);   // 32767
    int np   = (past + 1) / PAGE;                // 2048

    gemv_qkv_k<<<768, 256>>>(Wq, Wk, Wv, x);
    reduce_rope_k<<<QKV_N / 256, 256>>>(past);
    score_k<<<np / 4, 256>>>(kc, np);
    topk_k<<<H_HEADS, 512>>>(np);
    attn_partial_k<<<H_HEADS * NCHUNK, 256>>>(kc, vc, past);
    gemv_o_k<<<512, 256>>>(Wo);
    reduce_out_k<<<HID / 256, 256>>>(out);
}